// round 15
// baseline (speedup 1.0000x reference)
#include <cuda_runtime.h>
#include <cuda_bf16.h>

// Problem shape (fixed by reference setup_inputs)
#define B 64
#define T 4096
#define H 512

#define OCHUNKS 4            // o-split of the v computation
#define NTILE   64           // t-values per scores block
#define NTILES  (T / NTILE)  // 64 tiles per b == 64 v-pieces per b

// Scratch (no allocation allowed in kernel_launch)
__device__ float  g_vpart[OCHUNKS][B][H];   // partial v per o-chunk
__device__ float  g_scores[B * T];          // raw scores [B, T]
__device__ float2 g_bpart[B][NTILES];       // per-(b,tile) (max, sumexp)
__device__ int    g_ready[B];               // v-piece arrival counters
                                            // (zero-init; scale kernel resets)

// PDL: wait for the upstream grid's completion trigger (sm_90+)
__device__ __forceinline__ void griddep_wait() {
    asm volatile("griddepcontrol.wait;" ::: "memory");
}

// online-softmax combine
__device__ __forceinline__ float2 sm_combine(float2 a, float2 c) {
    const float m = fmaxf(a.x, c.x);
    float2 r;
    r.x = m;
    r.y = a.y * __expf(a.x - m) + c.y * __expf(c.x - m);
    return r;
}

// ---------------------------------------------------------------------------
// Fused kernel: each block (tile, b) FIRST computes one of the 64 v-pieces
// for its own batch b (htile = tile&15 -> 32 h's, oc = tile>>4 -> 128 o's),
// publishes it, and spins until all 64 sibling pieces for b have arrived
// (waiting set == contributing set: the 64 blocks of a b are contiguous
// block-ids and co-scheduled -> no deadlock). Then the proven streaming
// scores loop (MLP_p1=4, shfl-in-loop, __ldcs) + (m,sumexp) tile partial.
// W is L2-resident after the first b's reads; per-block proj cost hides
// under the other blocks' DRAM streaming.
// ---------------------------------------------------------------------------
__global__ void __launch_bounds__(256)
scores_kernel(const float* __restrict__ enc,
              const float* __restrict__ hidden,
              const float* __restrict__ W) {
    const int b    = blockIdx.y;
    const int tile = blockIdx.x;          // 64 t-values per block
    const int tid  = threadIdx.x;         // 256
    const int warp = tid >> 5;
    const int lane = tid & 31;

    // ---- phase 1: compute v-piece (htile, oc) for batch b ----
    const int htile = tile & 15;          // h-tile: 32 h's
    const int oc    = tile >> 4;          // o-chunk: 128 o's

    __shared__ float sh[128];             // hidden[b, oc*128 : oc*128+128]
    if (tid < 128) sh[tid] = hidden[(size_t)b * H + oc * 128 + tid];
    __syncthreads();

    {
        // warp 'warp' covers o's [warp*16, warp*16+16); lane = h within tile
        const float* __restrict__ wp =
            W + (size_t)(oc * 128 + warp * 16) * H + htile * 32 + lane;
        const int ol = warp * 16;
        float acc = 0.0f;
#pragma unroll
        for (int o = 0; o < 16; ++o)
            acc += sh[ol + o] * wp[(size_t)o * H];

        __shared__ float part[8][32];
        part[warp][lane] = acc;
        __syncthreads();
        if (tid < 32) {
            float r = 0.0f;
#pragma unroll
            for (int g = 0; g < 8; ++g) r += part[g][tid];
            g_vpart[oc][b][htile * 32 + tid] = r;
        }
        __threadfence();                  // publish the piece
        __syncthreads();
        if (tid == 0) atomicAdd(&g_ready[b], 1);
    }

    // ---- phase 2: wait for all 64 pieces of this b ----
    if (tid == 0) {
        while (atomicAdd(&g_ready[b], 0) < NTILES) { }
    }
    __syncthreads();
    __threadfence();                      // acquire sibling writes

    // ---- phase 3: proven streaming scores loop ----
    __shared__ float sv[H];
    {
        const float2 p0 = reinterpret_cast<const float2*>(g_vpart[0][b])[tid];
        const float2 p1 = reinterpret_cast<const float2*>(g_vpart[1][b])[tid];
        const float2 p2 = reinterpret_cast<const float2*>(g_vpart[2][b])[tid];
        const float2 p3 = reinterpret_cast<const float2*>(g_vpart[3][b])[tid];
        float2 s;
        s.x = (p0.x + p1.x) + (p2.x + p3.x);
        s.y = (p0.y + p1.y) + (p2.y + p3.y);
        reinterpret_cast<float2*>(sv)[tid] = s;
    }
    __syncthreads();

    const float4* __restrict__ vb = reinterpret_cast<const float4*>(sv);
    const float4* __restrict__ base =
        reinterpret_cast<const float4*>(enc + (size_t)b * T * H);

    __shared__ float s_acc[64];           // this block's 64 raw scores

#pragma unroll
    for (int i = 0; i < 8; ++i) {
        const int t = tile * 64 + warp * 8 + i;
        const float4* __restrict__ row = base + (size_t)t * (H / 4);

        float acc = 0.0f;
#pragma unroll
        for (int k = 0; k < 4; ++k) {
            const float4 x = __ldcs(row + lane + k * 32);
            const float4 w = vb[lane + k * 32];
            acc += x.x * w.x + x.y * w.y + x.z * w.z + x.w * w.w;
        }
#pragma unroll
        for (int off = 16; off; off >>= 1)
            acc += __shfl_xor_sync(0xffffffffu, acc, off);
        if (lane == 0) {
            g_scores[b * T + t] = acc;
            s_acc[warp * 8 + i] = acc;
        }
    }

    // block tail: (m, sumexp) over the 64 scores (off the load path)
    __syncthreads();
    if (tid < 32) {
        const float v0 = s_acc[tid];
        const float v1 = s_acc[tid + 32];
        float m = fmaxf(v0, v1);
#pragma unroll
        for (int off = 16; off; off >>= 1)
            m = fmaxf(m, __shfl_xor_sync(0xffffffffu, m, off));
        float e = __expf(v0 - m) + __expf(v1 - m);
#pragma unroll
        for (int off = 16; off; off >>= 1)
            e += __shfl_xor_sync(0xffffffffu, e, off);
        if (tid == 0) {
            float2 r; r.x = m; r.y = e;
            g_bpart[b][tile] = r;
        }
    }
}

// ---------------------------------------------------------------------------
// Kernel 2: scale pass (PDL on scores). Grid (T/1024, B) = 256 blocks x 256
// threads. Combine 64 tile partials (L2 hits), exp(x-m)/S, and reset the
// ready counters for the next graph replay.
// ---------------------------------------------------------------------------
__global__ void __launch_bounds__(256)
scale_kernel(float* __restrict__ out) {
    const int b   = blockIdx.y;
    const int seg = blockIdx.x;           // 1024 t-values per block
    const int tid = threadIdx.x;          // 256

    griddep_wait();                       // scores results visible after this

    if (seg == 0 && tid == 0) g_ready[b] = 0;   // replay-safe reset

    __shared__ float2 ms;
    if (tid < 32) {
        float2 v = sm_combine(g_bpart[b][tid], g_bpart[b][tid + 32]);
#pragma unroll
        for (int off = 16; off; off >>= 1) {
            float2 o;
            o.x = __shfl_xor_sync(0xffffffffu, v.x, off);
            o.y = __shfl_xor_sync(0xffffffffu, v.y, off);
            v = sm_combine(v, o);
        }
        if (tid == 0) ms = v;
    }
    __syncthreads();

    const float m   = ms.x;
    const float inv = 1.0f / ms.y;

    const int idx = b * T + seg * 1024 + tid * 4;
    const float4 x = *reinterpret_cast<const float4*>(g_scores + idx);
    float4 y;
    y.x = __expf(x.x - m) * inv;
    y.y = __expf(x.y - m) * inv;
    y.z = __expf(x.z - m) * inv;
    y.w = __expf(x.w - m) * inv;
    *reinterpret_cast<float4*>(out + idx) = y;
}

// ---------------------------------------------------------------------------
extern "C" void kernel_launch(void* const* d_in, const int* in_sizes, int n_in,
                              void* d_out, int out_size) {
    const float* hidden = (const float*)d_in[0];   // [B, H]
    const float* enc    = (const float*)d_in[1];   // [B, T, H]
    const float* W      = (const float*)d_in[2];   // [H, H]
    // d_in[3] = bias: cancels under softmax, unused.
    float* out = (float*)d_out;                    // [B, 1, T]

    // Kernel 1: fused v + scores
    {
        dim3 grid(T / NTILE, B);
        scores_kernel<<<grid, 256>>>(enc, hidden, W);
    }

    // Kernel 2: scale, PDL on scores
    {
        cudaLaunchAttribute attrs[1];
        attrs[0].id = cudaLaunchAttributeProgrammaticStreamSerialization;
        attrs[0].val.programmaticStreamSerializationAllowed = 1;

        cudaLaunchConfig_t cfg = {};
        cfg.gridDim  = dim3(T / 1024, B);
        cfg.blockDim = dim3(256);
        cfg.dynamicSmemBytes = 0;
        cfg.stream = 0;
        cfg.attrs = attrs;
        cfg.numAttrs = 1;
        cudaLaunchKernelEx(&cfg, scale_kernel, out);
    }
}

// round 16
// speedup vs baseline: 1.0712x; 1.0712x over previous
#include <cuda_runtime.h>
#include <cuda_bf16.h>

// Problem shape (fixed by reference setup_inputs)
#define B 64
#define T 4096
#define H 512

#define OCHUNKS 4            // o-split across blocks in proj
#define NTILE   64           // t-values per scores block
#define NTILES  (T / NTILE)  // 64 tiles per b

// Scratch (no allocation allowed in kernel_launch)
__device__ float  g_vpart[OCHUNKS][B][H];   // partial v per o-chunk
__device__ float  g_scores[B * T];          // raw scores [B, T]
__device__ float2 g_bpart[B][NTILES];       // per-(b,tile) (max, sumexp)

// PDL: wait for the upstream grid's completion trigger (sm_90+)
__device__ __forceinline__ void griddep_wait() {
    asm volatile("griddepcontrol.wait;" ::: "memory");
}

// online-softmax combine
__device__ __forceinline__ float2 sm_combine(float2 a, float2 c) {
    const float m = fmaxf(a.x, c.x);
    float2 r;
    r.x = m;
    r.y = a.y * __expf(a.x - m) + c.y * __expf(c.x - m);
    return r;
}

// ---------------------------------------------------------------------------
// Kernel 1: partial v: g_vpart[z][b,h] = sum_{o in chunk z} hidden[b,o]*W[o,h]
// Grid: (H/32, B/4, 4) = 1024 blocks x 256 threads. BTILE=4, hidden staged
// transposed as float4 (1 broadcast LDS.128 per o-step). W L2 traffic = 16MB.
// ---------------------------------------------------------------------------
__global__ void __launch_bounds__(256, 8)
proj_hidden_kernel(const float* __restrict__ hidden,
                   const float* __restrict__ W) {
    const int b0 = blockIdx.y * 4;
    const int h0 = blockIdx.x * 32;
    const int oc = blockIdx.z;            // o-chunk, 128 o's
    const int hl = threadIdx.x & 31;      // h lane
    const int og = threadIdx.x >> 5;      // o-group 0..7 (warp-uniform)

    __shared__ float4 shv[128];           // shv[o] = {h[b0..b0+3] at o}
    {
        const int r = threadIdx.x >> 6;           // 0..3 (b row)
        const int c = threadIdx.x & 63;           // float2 slot
        const float2 hv = reinterpret_cast<const float2*>(
            hidden + (size_t)(b0 + r) * H + oc * 128)[c];
        reinterpret_cast<float*>(&shv[2 * c])[r]     = hv.x;
        reinterpret_cast<float*>(&shv[2 * c + 1])[r] = hv.y;
    }
    __syncthreads();

    const int obase = oc * 128 + og * 16;
    const float* __restrict__ wp = W + (size_t)obase * H + h0 + hl;
    const int ol = og * 16;
    float acc0 = 0.0f, acc1 = 0.0f, acc2 = 0.0f, acc3 = 0.0f;
#pragma unroll
    for (int o = 0; o < 16; ++o) {
        const float  w = wp[(size_t)o * H];
        const float4 h4 = shv[ol + o];    // broadcast, conflict-free
        acc0 += h4.x * w;
        acc1 += h4.y * w;
        acc2 += h4.z * w;
        acc3 += h4.w * w;
    }

    __shared__ float part[8][4][32];
    part[og][0][hl] = acc0;
    part[og][1][hl] = acc1;
    part[og][2][hl] = acc2;
    part[og][3][hl] = acc3;
    __syncthreads();
    if (threadIdx.x < 128) {
        const int bb = threadIdx.x >> 5;   // 0..3
        const int hh = threadIdx.x & 31;
        float r = 0.0f;
#pragma unroll
        for (int g = 0; g < 8; ++g) r += part[g][bb][hh];
        g_vpart[oc][b0 + bb][h0 + hh] = r;
    }
}

// ---------------------------------------------------------------------------
// Kernel 2: scores[b,t] = enc[b,t,:] . v[b,:]. PDL-launched: blocks dispatch
// while proj runs. The FIRST t-iteration's enc loads are issued BEFORE
// griddep_wait (they don't depend on proj), so predispatched blocks stream
// DRAM in proj's shadow. Inner loop: MLP_p1=4, shfl-in-loop (proven).
// ---------------------------------------------------------------------------
__global__ void __launch_bounds__(256)
scores_kernel(const float* __restrict__ enc) {
    const int b    = blockIdx.y;
    const int tile = blockIdx.x;          // 64 t-values per block
    const int tid  = threadIdx.x;         // 256
    const int warp = tid >> 5;
    const int lane = tid & 31;

    const float4* __restrict__ base =
        reinterpret_cast<const float4*>(enc + (size_t)b * T * H);

    // ---- prefetch t(i=0) BEFORE the PDL wait: no proj dependency ----
    const float4* __restrict__ row0 =
        base + (size_t)(tile * 64 + warp * 8) * (H / 4);
    const float4 e0 = __ldcs(row0 + lane);
    const float4 e1 = __ldcs(row0 + lane + 32);
    const float4 e2 = __ldcs(row0 + lane + 64);
    const float4 e3 = __ldcs(row0 + lane + 96);

    griddep_wait();                       // proj results visible after this

    __shared__ float sv[H];
    {
        const float2 p0 = reinterpret_cast<const float2*>(g_vpart[0][b])[tid];
        const float2 p1 = reinterpret_cast<const float2*>(g_vpart[1][b])[tid];
        const float2 p2 = reinterpret_cast<const float2*>(g_vpart[2][b])[tid];
        const float2 p3 = reinterpret_cast<const float2*>(g_vpart[3][b])[tid];
        float2 s;
        s.x = (p0.x + p1.x) + (p2.x + p3.x);
        s.y = (p0.y + p1.y) + (p2.y + p3.y);
        reinterpret_cast<float2*>(sv)[tid] = s;
    }
    __syncthreads();

    const float4* __restrict__ vb = reinterpret_cast<const float4*>(sv);
    __shared__ float s_acc[64];           // this block's 64 raw scores

    // ---- i = 0 from the prefetched registers ----
    {
        const float4 w0 = vb[lane], w1 = vb[lane + 32],
                     w2 = vb[lane + 64], w3 = vb[lane + 96];
        float acc = e0.x * w0.x + e0.y * w0.y + e0.z * w0.z + e0.w * w0.w;
        acc      += e1.x * w1.x + e1.y * w1.y + e1.z * w1.z + e1.w * w1.w;
        acc      += e2.x * w2.x + e2.y * w2.y + e2.z * w2.z + e2.w * w2.w;
        acc      += e3.x * w3.x + e3.y * w3.y + e3.z * w3.z + e3.w * w3.w;
#pragma unroll
        for (int off = 16; off; off >>= 1)
            acc += __shfl_xor_sync(0xffffffffu, acc, off);
        if (lane == 0) {
            g_scores[b * T + tile * 64 + warp * 8] = acc;
            s_acc[warp * 8] = acc;
        }
    }

    // ---- i = 1..7: proven streaming loop ----
#pragma unroll
    for (int i = 1; i < 8; ++i) {
        const int t = tile * 64 + warp * 8 + i;
        const float4* __restrict__ row = base + (size_t)t * (H / 4);

        float acc = 0.0f;
#pragma unroll
        for (int k = 0; k < 4; ++k) {
            const float4 x = __ldcs(row + lane + k * 32);
            const float4 w = vb[lane + k * 32];
            acc += x.x * w.x + x.y * w.y + x.z * w.z + x.w * w.w;
        }
#pragma unroll
        for (int off = 16; off; off >>= 1)
            acc += __shfl_xor_sync(0xffffffffu, acc, off);
        if (lane == 0) {
            g_scores[b * T + t] = acc;
            s_acc[warp * 8 + i] = acc;
        }
    }

    // block tail: (m, sumexp) over the 64 scores (off the load path)
    __syncthreads();
    if (tid < 32) {
        const float v0 = s_acc[tid];
        const float v1 = s_acc[tid + 32];
        float m = fmaxf(v0, v1);
#pragma unroll
        for (int off = 16; off; off >>= 1)
            m = fmaxf(m, __shfl_xor_sync(0xffffffffu, m, off));
        float e = __expf(v0 - m) + __expf(v1 - m);
#pragma unroll
        for (int off = 16; off; off >>= 1)
            e += __shfl_xor_sync(0xffffffffu, e, off);
        if (tid == 0) {
            float2 r; r.x = m; r.y = e;
            g_bpart[b][tile] = r;
        }
    }
}

// ---------------------------------------------------------------------------
// Kernel 3: scale pass (PDL-launched). Grid (T/1024, B) = 256 blocks x 256
// threads. Combine 64 tile partials (L2 hits), then exp(x-m)/S.
// ---------------------------------------------------------------------------
__global__ void __launch_bounds__(256)
scale_kernel(float* __restrict__ out) {
    const int b   = blockIdx.y;
    const int seg = blockIdx.x;           // 1024 t-values per block
    const int tid = threadIdx.x;          // 256

    griddep_wait();                       // scores results visible after this

    __shared__ float2 ms;
    if (tid < 32) {
        float2 v = sm_combine(g_bpart[b][tid], g_bpart[b][tid + 32]);
#pragma unroll
        for (int off = 16; off; off >>= 1) {
            float2 o;
            o.x = __shfl_xor_sync(0xffffffffu, v.x, off);
            o.y = __shfl_xor_sync(0xffffffffu, v.y, off);
            v = sm_combine(v, o);
        }
        if (tid == 0) ms = v;
    }
    __syncthreads();

    const float m   = ms.x;
    const float inv = 1.0f / ms.y;

    const int idx = b * T + seg * 1024 + tid * 4;
    const float4 x = *reinterpret_cast<const float4*>(g_scores + idx);
    float4 y;
    y.x = __expf(x.x - m) * inv;
    y.y = __expf(x.y - m) * inv;
    y.z = __expf(x.z - m) * inv;
    y.w = __expf(x.w - m) * inv;
    *reinterpret_cast<float4*>(out + idx) = y;
}

// ---------------------------------------------------------------------------
extern "C" void kernel_launch(void* const* d_in, const int* in_sizes, int n_in,
                              void* d_out, int out_size) {
    const float* hidden = (const float*)d_in[0];   // [B, H]
    const float* enc    = (const float*)d_in[1];   // [B, T, H]
    const float* W      = (const float*)d_in[2];   // [H, H]
    // d_in[3] = bias: cancels under softmax, unused.
    float* out = (float*)d_out;                    // [B, 1, T]

    // Kernel 1: plain launch
    {
        dim3 grid(H / 32, B / 4, OCHUNKS);
        proj_hidden_kernel<<<grid, 256>>>(hidden, W);
    }

    // PDL attribute shared by the two dependent launches
    cudaLaunchAttribute attrs[1];
    attrs[0].id = cudaLaunchAttributeProgrammaticStreamSerialization;
    attrs[0].val.programmaticStreamSerializationAllowed = 1;

    // Kernel 2: scores, PDL on proj
    {
        cudaLaunchConfig_t cfg = {};
        cfg.gridDim  = dim3(T / NTILE, B);
        cfg.blockDim = dim3(256);
        cfg.dynamicSmemBytes = 0;
        cfg.stream = 0;
        cfg.attrs = attrs;
        cfg.numAttrs = 1;
        cudaLaunchKernelEx(&cfg, scores_kernel, enc);
    }

    // Kernel 3: scale, PDL on scores
    {
        cudaLaunchConfig_t cfg = {};
        cfg.gridDim  = dim3(T / 1024, B);
        cfg.blockDim = dim3(256);
        cfg.dynamicSmemBytes = 0;
        cfg.stream = 0;
        cfg.attrs = attrs;
        cfg.numAttrs = 1;
        cudaLaunchKernelEx(&cfg, scale_kernel, out);
    }
}